// round 1
// baseline (speedup 1.0000x reference)
#include <cuda_runtime.h>
#include <math.h>

// Problem constants
#define N       16384
#define LOG2B   18
#define B       (1 << LOG2B)     // 262144 buckets
#define F       64                // fine buckets per coarse chunk
#define NC      (B / F)           // 4096 coarse chunks

// Static device scratch (no allocation allowed)
__device__ float g_W[B];          // bucket-weighted exp sums
__device__ int   g_count[B];      // bucket occupancy
__device__ float g_e[N];          // exp(theta)
__device__ int   g_b[N];          // bucket of each item
__device__ float g_C[NC];         // coarse sums
__device__ float g_CP[NC];        // exclusive coarse prefix
__device__ int   g_L[N];          // collision list
__device__ int   g_Lsize;
__device__ float g_total;
__device__ float g_contrib[N];

// K0: zero scratch
__global__ void k_zero() {
    int idx = blockIdx.x * blockDim.x + threadIdx.x;
    if (idx < B) {
        g_W[idx] = 0.0f;
        g_count[idx] = 0;
    }
    if (idx == 0) g_Lsize = 0;
}

// K1: exp + scatter into buckets
__global__ void k_scatter(const float* __restrict__ theta,
                          const float* __restrict__ dur) {
    int i = blockIdx.x * blockDim.x + threadIdx.x;
    if (i >= N) return;
    float e = expf(theta[i]);
    float d = dur[i];
    unsigned int b = (unsigned int)(d * (float)B);
    if (b >= B) b = B - 1;
    g_e[i] = e;
    g_b[i] = (int)b;
    atomicAdd(&g_W[b], e);
    atomicAdd(&g_count[b], 1);
}

// K2: build collision list (items sharing a bucket with someone else)
__global__ void k_collide() {
    int i = blockIdx.x * blockDim.x + threadIdx.x;
    if (i >= N) return;
    int b = g_b[i];
    if (g_count[b] >= 2) {
        int pos = atomicAdd(&g_Lsize, 1);
        g_L[pos] = i;
    }
}

// K3: coarse reduce: C[k] = sum of W[k*F .. k*F+F)
__global__ void k_coarse() {
    int k = blockIdx.x;          // 4096 blocks, 32 threads
    int t = threadIdx.x;
    float v = g_W[k * F + t] + g_W[k * F + t + 32];
    #pragma unroll
    for (int off = 16; off > 0; off >>= 1)
        v += __shfl_down_sync(0xFFFFFFFFu, v, off);
    if (t == 0) g_C[k] = v;
}

// K4: single-block exclusive scan over NC=4096 coarse sums
__global__ void k_scan() {
    __shared__ float s[1024];
    int t = threadIdx.x;          // 1024 threads, 4 elems each
    float l0 = g_C[4 * t + 0];
    float l1 = g_C[4 * t + 1];
    float l2 = g_C[4 * t + 2];
    float l3 = g_C[4 * t + 3];
    float lsum = l0 + l1 + l2 + l3;
    s[t] = lsum;
    __syncthreads();
    // Hillis-Steele inclusive scan over 1024 partials
    #pragma unroll
    for (int off = 1; off < 1024; off <<= 1) {
        float v = (t >= off) ? s[t - off] : 0.0f;
        __syncthreads();
        s[t] += v;
        __syncthreads();
    }
    float excl = s[t] - lsum;     // exclusive prefix of this thread's segment
    g_CP[4 * t + 0] = excl;
    g_CP[4 * t + 1] = excl + l0;
    g_CP[4 * t + 2] = excl + l0 + l1;
    g_CP[4 * t + 3] = excl + l0 + l1 + l2;
    if (t == 1023) g_total = excl + lsum;  // grand total
}

// K5: per-item risk sum + loss contribution
__global__ void k_item(const float* __restrict__ theta,
                       const float* __restrict__ dur,
                       const float* __restrict__ ev) {
    int i = blockIdx.x * blockDim.x + threadIdx.x;
    if (i >= N) return;
    int b = g_b[i];
    int k = b >> 6;               // coarse chunk
    float S = g_CP[k];            // all buckets in chunks < k
    for (int bb = k * F; bb < b; ++bb)
        S += g_W[bb];             // strictly-smaller buckets in own chunk
    if (g_count[b] >= 2) {
        // same-bucket, strictly-smaller-duration items (all live in g_L)
        float di = dur[i];
        int Ls = g_Lsize;
        for (int j = 0; j < Ls; ++j) {
            int jj = g_L[j];
            if (g_b[jj] == b && dur[jj] < di)
                S += g_e[jj];
        }
    }
    float risk = g_total - S;     // sum over d_j >= d_i (ties included)
    g_contrib[i] = (theta[i] - logf(risk)) * ev[i];
}

// K6: deterministic single-block reduction -> -mean
__global__ void k_reduce(float* __restrict__ out) {
    __shared__ float s[1024];
    int t = threadIdx.x;
    float v = 0.0f;
    #pragma unroll
    for (int j = 0; j < N / 1024; ++j)
        v += g_contrib[t + j * 1024];
    s[t] = v;
    __syncthreads();
    for (int off = 512; off > 0; off >>= 1) {
        if (t < off) s[t] += s[t + off];
        __syncthreads();
    }
    if (t == 0) out[0] = -s[0] / (float)N;
}

extern "C" void kernel_launch(void* const* d_in, const int* in_sizes, int n_in,
                              void* d_out, int out_size) {
    const float* theta = (const float*)d_in[0];  // hazard_pred (N,1)
    const float* dur   = (const float*)d_in[1];  // durations (N,)
    const float* ev    = (const float*)d_in[2];  // events (N,)
    float* out = (float*)d_out;

    k_zero<<<B / 256, 256>>>();
    k_scatter<<<N / 256, 256>>>(theta, dur);
    k_collide<<<N / 256, 256>>>();
    k_coarse<<<NC, 32>>>();
    k_scan<<<1, 1024>>>();
    k_item<<<N / 256, 256>>>(theta, dur, ev);
    k_reduce<<<1, 1024>>>(out);
}

// round 2
// speedup vs baseline: 2.5751x; 2.5751x over previous
#include <cuda_runtime.h>
#include <math.h>

#define N    16384
#define BKT  16384          // buckets (lambda = 1)
#define T    1024           // threads
#define IPT  (N / T)        // 16 items per thread
#define BPT  (BKT / T)      // 16 buckets per thread

// smem layout (bytes):
//   W    : float[BKT]   @ 0        (64KB)  bucket exp-sums, then exclusive prefix
//   head : int[BKT]     @ 65536    (64KB)  chain heads (-1 = empty)
//   nxt  : ushort[N]    @ 131072   (32KB)  chain next (0xFFFF = end)
//   scan : float[T]     @ 163840   (4KB)   block-scan workspace
#define SMEM_BYTES (65536 + 65536 + 32768 + 4096 + 16)

extern __shared__ char smem_raw[];

__device__ __forceinline__ int bucket_of(float d) {
    int b = (int)(d * (float)BKT);
    if (b >= BKT) b = BKT - 1;
    if (b < 0) b = 0;
    return b;
}

__global__ void __launch_bounds__(T, 1)
cox_fused_kernel(const float* __restrict__ theta,
                 const float* __restrict__ dur,
                 const float* __restrict__ ev,
                 float* __restrict__ out) {
    float*          W    = (float*)(smem_raw);
    int*            head = (int*)(smem_raw + 65536);
    unsigned short* nxt  = (unsigned short*)(smem_raw + 131072);
    float*          scan = (float*)(smem_raw + 163840);
    __shared__ float s_total;

    int t = threadIdx.x;

    // ---- Phase 1: zero buckets / chain heads ----
    #pragma unroll
    for (int k = 0; k < BPT; ++k) {
        int b = t + k * T;
        W[b] = 0.0f;
        head[b] = -1;
    }
    __syncthreads();

    // ---- Phase 2: scatter exp(theta) into buckets + build chains ----
    #pragma unroll
    for (int k = 0; k < IPT; ++k) {
        int i = t + k * T;                 // coalesced
        float th = theta[i];
        float d  = dur[i];
        float e  = __expf(th) ;
        // use precise expf for accuracy of sums
        e = expf(th);
        int b = bucket_of(d);
        atomicAdd(&W[b], e);
        int old = atomicExch(&head[b], i);
        nxt[i] = (unsigned short)old;      // -1 -> 0xFFFF sentinel
    }
    __syncthreads();

    // ---- Phase 3: exclusive prefix over 16384 buckets ----
    // thread t owns buckets [16t, 16t+16)
    float loc[BPT];
    float run = 0.0f;
    #pragma unroll
    for (int k = 0; k < BPT; ++k) {
        loc[k] = run;                       // local exclusive prefix
        run += W[t * BPT + k];
    }
    scan[t] = run;                          // segment total
    __syncthreads();
    // Hillis-Steele inclusive scan over 1024 segment totals
    #pragma unroll
    for (int off = 1; off < T; off <<= 1) {
        float v = (t >= off) ? scan[t - off] : 0.0f;
        __syncthreads();
        scan[t] += v;
        __syncthreads();
    }
    float seg_excl = scan[t] - run;         // exclusive prefix of segment
    if (t == T - 1) s_total = scan[t];      // grand total
    __syncthreads();                        // everyone done reading W
    #pragma unroll
    for (int k = 0; k < BPT; ++k)
        W[t * BPT + k] = seg_excl + loc[k]; // overwrite with exclusive prefix
    __syncthreads();

    float total = s_total;

    // ---- Phase 4: per-item risk sum + loss contribution ----
    float acc = 0.0f;
    #pragma unroll
    for (int k = 0; k < IPT; ++k) {
        int i = t + k * T;
        float th = theta[i];                // L1 hits
        float d  = dur[i];
        float e_ = ev[i];
        int b = bucket_of(d);
        float S = W[b];                     // mass in strictly-smaller buckets
        // same-bucket items with strictly smaller duration
        int j = head[b];
        while (j != -1) {
            if (j != i) {
                float dj = dur[j];
                if (dj < d) S += expf(theta[j]);
            }
            unsigned short nj = nxt[j];
            j = (nj == 0xFFFFu) ? -1 : (int)nj;
        }
        float risk = total - S;             // sum over d_j >= d_i (ties incl.)
        acc += (th - logf(risk)) * e_;
    }
    __syncthreads();                        // done with scan[] reuse below

    // ---- Phase 5: block reduction -> -mean ----
    scan[t] = acc;
    __syncthreads();
    for (int off = T / 2; off > 0; off >>= 1) {
        if (t < off) scan[t] += scan[t + off];
        __syncthreads();
    }
    if (t == 0) out[0] = -scan[0] / (float)N;
}

extern "C" void kernel_launch(void* const* d_in, const int* in_sizes, int n_in,
                              void* d_out, int out_size) {
    const float* theta = (const float*)d_in[0];  // hazard_pred (N,1)
    const float* dur   = (const float*)d_in[1];  // durations (N,)
    const float* ev    = (const float*)d_in[2];  // events (N,)
    float* out = (float*)d_out;

    static int configured = 0;
    if (!configured) {
        cudaFuncSetAttribute(cox_fused_kernel,
                             cudaFuncAttributeMaxDynamicSharedMemorySize,
                             SMEM_BYTES);
        configured = 1;
    }
    cox_fused_kernel<<<1, T, SMEM_BYTES>>>(theta, dur, ev, out);
}

// round 3
// speedup vs baseline: 4.9388x; 1.9179x over previous
#include <cuda_runtime.h>
#include <math.h>

#define N    16384
#define BKT  8192           // buckets (lambda = 2)
#define T    1024           // threads
#define IPT  (N / T)        // 16 items per thread
#define BPT  (BKT / T)      // 8 buckets per thread

// dynamic smem layout (bytes):
//   W    : float[BKT]    @ 0       (32KB)  bucket exp-sums -> exclusive prefix
//   head : int[BKT]      @ 32768   (32KB)  chain heads (-1 = empty)
//   nxt  : ushort[N]     @ 65536   (32KB)  chain next (0xFFFF = end)
//   de   : float2[N]     @ 98304   (128KB) {duration, exp(theta)} per item
#define SMEM_BYTES (32768 + 32768 + 32768 + 131072)

extern __shared__ char smem_raw[];

__device__ __forceinline__ int bucket_of(float d) {
    int b = (int)(d * (float)BKT);
    if (b >= BKT) b = BKT - 1;
    if (b < 0) b = 0;
    return b;
}

__global__ void __launch_bounds__(T, 1)
cox_fused_kernel(const float* __restrict__ theta,
                 const float* __restrict__ dur,
                 const float* __restrict__ ev,
                 float* __restrict__ out) {
    float*          W    = (float*)(smem_raw);
    int*            head = (int*)(smem_raw + 32768);
    unsigned short* nxt  = (unsigned short*)(smem_raw + 65536);
    float2*         de   = (float2*)(smem_raw + 98304);

    __shared__ float warpTot[32];
    __shared__ float warpPre[32];
    __shared__ float s_total;

    const int t    = threadIdx.x;
    const int lane = t & 31;
    const int wid  = t >> 5;

    // ---- Phase 1: zero buckets / chain heads ----
    #pragma unroll
    for (int k = 0; k < BPT; ++k) {
        int b = t + k * T;
        W[b] = 0.0f;
        head[b] = -1;
    }
    __syncthreads();

    // ---- Phase 2: scatter exp(theta); build chains; accumulate ev*theta ----
    float acc = 0.0f;   // will hold sum of ev*theta - ev*log(risk) (this thread)
    #pragma unroll
    for (int k = 0; k < IPT; ++k) {
        int i = t + k * T;                 // coalesced
        float th = theta[i];
        float d  = dur[i];
        float e_ = ev[i];
        float e  = __expf(th);
        acc += e_ * th;
        de[i] = make_float2(d, e);
        int b = bucket_of(d);
        atomicAdd(&W[b], e);
        int old = atomicExch(&head[b], i);
        nxt[i] = (unsigned short)old;      // -1 -> 0xFFFF sentinel
    }
    __syncthreads();

    // ---- Phase 3: exclusive prefix over 8192 buckets (warp-shuffle scan) ----
    float loc[BPT];
    float run = 0.0f;
    #pragma unroll
    for (int k = 0; k < BPT; ++k) {
        loc[k] = run;                       // local exclusive prefix
        run += W[t * BPT + k];
    }
    // warp inclusive scan of run
    float incl = run;
    #pragma unroll
    for (int off = 1; off < 32; off <<= 1) {
        float v = __shfl_up_sync(0xFFFFFFFFu, incl, off);
        if (lane >= off) incl += v;
    }
    if (lane == 31) warpTot[wid] = incl;
    __syncthreads();
    if (wid == 0) {
        float v = warpTot[lane];
        float winc = v;
        #pragma unroll
        for (int off = 1; off < 32; off <<= 1) {
            float u = __shfl_up_sync(0xFFFFFFFFu, winc, off);
            if (lane >= off) winc += u;
        }
        warpPre[lane] = winc - v;           // exclusive warp prefix
        if (lane == 31) s_total = winc;     // grand total
    }
    __syncthreads();
    float seg_excl = warpPre[wid] + (incl - run);
    #pragma unroll
    for (int k = 0; k < BPT; ++k)
        W[t * BPT + k] = seg_excl + loc[k]; // overwrite with exclusive prefix
    float total = s_total;
    __syncthreads();

    // ---- Phase 4: per-item risk sum (all on-chip) ----
    #pragma unroll 4
    for (int k = 0; k < IPT; ++k) {
        int i = t + k * T;
        float2 me = de[i];
        float d = me.x;
        float e_ = ev[i];                   // coalesced global (L2)
        int b = bucket_of(d);
        float S = W[b];                     // mass in strictly-smaller buckets
        // same-bucket items with strictly smaller duration (smem chain walk)
        int j = head[b];
        while (j != -1) {
            if (j != i) {
                float2 oj = de[j];
                if (oj.x < d) S += oj.y;
            }
            unsigned short nj = nxt[j];
            j = (nj == 0xFFFFu) ? -1 : (int)nj;
        }
        float risk = total - S;             // sum over d_j >= d_i (ties incl.)
        acc -= e_ * __logf(risk);
    }

    // ---- Phase 5: reduction -> -mean ----
    #pragma unroll
    for (int off = 16; off > 0; off >>= 1)
        acc += __shfl_down_sync(0xFFFFFFFFu, acc, off);
    __syncthreads();                        // warpTot reuse safe
    if (lane == 0) warpTot[wid] = acc;
    __syncthreads();
    if (wid == 0) {
        float v = warpTot[lane];
        #pragma unroll
        for (int off = 16; off > 0; off >>= 1)
            v += __shfl_down_sync(0xFFFFFFFFu, v, off);
        if (lane == 0) out[0] = -v / (float)N;
    }
}

extern "C" void kernel_launch(void* const* d_in, const int* in_sizes, int n_in,
                              void* d_out, int out_size) {
    const float* theta = (const float*)d_in[0];  // hazard_pred (N,1)
    const float* dur   = (const float*)d_in[1];  // durations (N,)
    const float* ev    = (const float*)d_in[2];  // events (N,)
    float* out = (float*)d_out;

    static int configured = 0;
    if (!configured) {
        cudaFuncSetAttribute(cox_fused_kernel,
                             cudaFuncAttributeMaxDynamicSharedMemorySize,
                             SMEM_BYTES);
        configured = 1;
    }
    cox_fused_kernel<<<1, T, SMEM_BYTES>>>(theta, dur, ev, out);
}